// round 12
// baseline (speedup 1.0000x reference)
#include <cuda_runtime.h>
#include <cuda_bf16.h>
#include <math.h>
#include <stdint.h>

// ---------------------------------------------------------------------------
// GatedDeltaNet encoder. HMMA bf16 hi/lo GEMMs, blocked-tile layout,
// cp.async.bulk pipeline, fused SwiGLU epilogue, fused conv+l2norm.
// ---------------------------------------------------------------------------

#define B_    4
#define T_    1024
#define D_    1024
#define H_    16
#define ROWS  (B_ * T_)          // 4096
#define I_    2816
#define TWOI  (2 * I_)           // 5632

static constexpr size_t SZ        = (size_t)ROWS * D_;
static constexpr size_t OFF_H     = 0 * SZ;
static constexpr size_t OFF_QKV   = 1 * SZ;                  // [4096,3072]
static constexpr size_t OFF_Q     = 4 * SZ;
static constexpr size_t OFF_K     = 5 * SZ;
static constexpr size_t OFF_V     = 6 * SZ;
static constexpr size_t OFF_O     = 7 * SZ;
static constexpr size_t OFF_H2    = 8 * SZ;
static constexpr size_t OFF_BETA  = 9 * SZ;
static constexpr size_t OFF_G     = OFF_BETA + (size_t)ROWS * H_;
static constexpr size_t POOL_SZ   = OFF_G + (size_t)ROWS * H_;

static __device__ __align__(256) float g_pool[POOL_SZ];

static constexpr size_t S1  = (size_t)ROWS * D_;
static constexpr size_t S2  = (size_t)ROWS * I_;
static constexpr size_t W1  = (size_t)D_ * D_;
static constexpr size_t SWG = (size_t)TWOI * D_;
static constexpr size_t SWD = (size_t)D_ * I_;

static constexpr size_t BF_AH  = 0;
static constexpr size_t BF_AL  = 1 * S1;
static constexpr size_t BF_OH  = 2 * S1;
static constexpr size_t BF_OL  = 3 * S1;
static constexpr size_t BF_3H  = 4 * S1;
static constexpr size_t BF_3L  = 5 * S1;
static constexpr size_t BF_UH  = 6 * S1;
static constexpr size_t BF_UL  = 6 * S1 + S2;
static constexpr size_t BF_WQKVH = 6 * S1 + 2 * S2;
static constexpr size_t BF_WQKVL = BF_WQKVH + 3 * W1;
static constexpr size_t BF_WOH = BF_WQKVL + 3 * W1;
static constexpr size_t BF_WOL = BF_WOH + W1;
static constexpr size_t BF_WGH = BF_WOL + W1;
static constexpr size_t BF_WGL = BF_WGH + SWG;
static constexpr size_t BF_WDH = BF_WGL + SWG;
static constexpr size_t BF_WDL = BF_WDH + SWD;
static constexpr size_t BF_SZ  = BF_WDL + SWD;

static __device__ __align__(256) __nv_bfloat16 g_bf[BF_SZ];

// ---------------------------------------------------------------------------
__device__ __forceinline__ uint32_t smem_u32(const void* p) {
  uint32_t r;
  asm("{ .reg .u64 t; cvta.to.shared.u64 t, %1; cvt.u32.u64 %0, t; }"
      : "=r"(r) : "l"(p));
  return r;
}
__device__ __forceinline__ void mbar_init(uint32_t a, uint32_t c) {
  asm volatile("mbarrier.init.shared.b64 [%0], %1;" :: "r"(a), "r"(c) : "memory");
}
__device__ __forceinline__ void mbar_wait(uint32_t a, uint32_t par) {
  asm volatile(
      "{\n\t.reg .pred P;\n"
      "W%=:\n\tmbarrier.try_wait.parity.acquire.cta.shared::cta.b64 P, [%0], %1, 0x989680;\n"
      "\t@!P bra W%=;\n\t}"
      :: "r"(a), "r"(par) : "memory");
}
__device__ __forceinline__ void expect_tx(uint32_t bar, uint32_t bytes) {
  asm volatile("mbarrier.arrive.expect_tx.shared.b64 _, [%0], %1;"
               :: "r"(bar), "r"(bytes) : "memory");
}
__device__ __forceinline__ void bulk_ld(uint32_t dst, const void* src,
                                        uint32_t bytes, uint32_t bar) {
  asm volatile(
      "cp.async.bulk.shared::cluster.global.mbarrier::complete_tx::bytes "
      "[%0], [%1], %2, [%3];"
      :: "r"(dst), "l"(src), "r"(bytes), "r"(bar) : "memory");
}
__device__ __forceinline__ void ldsm4(uint32_t* r, uint32_t addr) {
  asm volatile(
      "ldmatrix.sync.aligned.m8n8.x4.shared.b16 {%0,%1,%2,%3}, [%4];"
      : "=r"(r[0]), "=r"(r[1]), "=r"(r[2]), "=r"(r[3])
      : "r"(addr));
}
__device__ __forceinline__ void mma16816(float* d, const uint32_t* a,
                                         const uint32_t* b) {
  asm volatile(
      "mma.sync.aligned.m16n8k16.row.col.f32.bf16.bf16.f32 "
      "{%0,%1,%2,%3}, {%4,%5,%6,%7}, {%8,%9}, {%0,%1,%2,%3};"
      : "+f"(d[0]), "+f"(d[1]), "+f"(d[2]), "+f"(d[3])
      : "r"(a[0]), "r"(a[1]), "r"(a[2]), "r"(a[3]), "r"(b[0]), "r"(b[1]));
}
__device__ __forceinline__ void split1(float v, __nv_bfloat16& h,
                                       __nv_bfloat16& l) {
  h = __float2bfloat16_rn(v);
  l = __float2bfloat16_rn(v - __bfloat162float(h));
}

// Blocked layout: [N/128][K/32] tiles of 128x32 bf16 (8192 B); rows 64 B;
// 16B units swizzled u ^= (r>>1)&3.
__device__ __forceinline__ size_t blk_off(int n, int k, int nK) {
  int nb = n >> 7, r = n & 127, kb = k >> 5;
  int unit = (k >> 3) & 3;
  int su = unit ^ ((r >> 1) & 3);
  size_t byte = ((size_t)(nb * nK + kb)) * 8192 + r * 64 + su * 16 + (k & 7) * 2;
  return byte >> 1;
}

// ---------------------------------------------------------------------------
// GEMM: C = (Ah+Al)(Bh+Bl)^T (+Res), or fused SwiGLU epilogue -> Uh/Ul.
// CTA 256x128, BK=32, 3 stages. 8 warps (4m x 2n), warp tile 64x64.
// ---------------------------------------------------------------------------
static constexpr int STG = 49152;
static constexpr int GEMM_SMEM = 1024 + 3 * STG;  // 148480

__global__ void __launch_bounds__(256, 1)
bf16gemm_kernel(const __nv_bfloat16* __restrict__ Ah,
                const __nv_bfloat16* __restrict__ Al,
                const __nv_bfloat16* __restrict__ Bh,
                const __nv_bfloat16* __restrict__ Bl,
                const float* __restrict__ Res, float* __restrict__ C,
                __nv_bfloat16* __restrict__ Uh, __nv_bfloat16* __restrict__ Ul,
                int N, int nK) {
  extern __shared__ __align__(16) char sm[];
  uint32_t sb = smem_u32(sm);
  const int tid = threadIdx.x;
  const int wid = tid >> 5, lid = tid & 31;
  const int gid = lid >> 2, tig = lid & 3;
  const int sub = lid >> 3, r8 = lid & 7;
  const int wm = wid >> 1, wn = wid & 1;
  const int mblk0 = blockIdx.y * 2;
  const int nblk = blockIdx.x;
  const int nc = nK;
  const int sx = (r8 >> 1) & 3;

  if (tid == 0) {
    mbar_init(sb + 0, 1);
    mbar_init(sb + 16, 1);
    mbar_init(sb + 32, 1);
  }
  __syncthreads();

  float acc[4][8][4];
#pragma unroll
  for (int i = 0; i < 4; i++)
#pragma unroll
    for (int j = 0; j < 8; j++)
#pragma unroll
      for (int r = 0; r < 4; r++) acc[i][j][r] = 0.f;

  if (tid == 0) {
#pragma unroll
    for (int s = 0; s < 3; s++) {
      uint32_t bar = sb + s * 16;
      uint32_t d = sb + 1024 + s * STG;
      expect_tx(bar, 49152);
      bulk_ld(d,         Ah + ((size_t)(mblk0 * nK + s)) * 4096, 8192, bar);
      bulk_ld(d + 8192,  Ah + ((size_t)((mblk0 + 1) * nK + s)) * 4096, 8192, bar);
      bulk_ld(d + 16384, Al + ((size_t)(mblk0 * nK + s)) * 4096, 8192, bar);
      bulk_ld(d + 24576, Al + ((size_t)((mblk0 + 1) * nK + s)) * 4096, 8192, bar);
      bulk_ld(d + 32768, Bh + ((size_t)(nblk * nK + s)) * 4096, 8192, bar);
      bulk_ld(d + 40960, Bl + ((size_t)(nblk * nK + s)) * 4096, 8192, bar);
    }
  }

  const uint32_t aRow = (uint32_t)((wm & 1) * 64 + (sub & 1) * 8 + r8) * 64;
  const uint32_t aTile = (uint32_t)(wm >> 1) * 8192;
  const uint32_t bRow = (uint32_t)(wn * 64 + (sub >> 1) * 8 + r8) * 64;

  for (int c = 0; c < nc; c++) {
    int st = c % 3;
    mbar_wait(sb + st * 16, (c / 3) & 1);

    uint32_t stage = sb + 1024 + st * STG;
    uint32_t aB = stage + aTile + aRow;
    uint32_t bB = stage + 32768 + bRow;
#pragma unroll
    for (int ks = 0; ks < 2; ks++) {
      uint32_t ua = (uint32_t)((ks * 2 + (sub >> 1)) ^ sx) << 4;
      uint32_t ub = (uint32_t)((ks * 2 + (sub & 1)) ^ sx) << 4;
      uint32_t ah[4][4], al[4][4], bh[8][2], bl[8][2];
#pragma unroll
      for (int mi = 0; mi < 4; mi++) {
        uint32_t ad = aB + mi * 1024 + ua;
        ldsm4(ah[mi], ad);
        ldsm4(al[mi], ad + 16384);
      }
#pragma unroll
      for (int np = 0; np < 4; np++) {
        uint32_t bd = bB + np * 1024 + ub;
        uint32_t th[4], tl[4];
        ldsm4(th, bd);
        ldsm4(tl, bd + 8192);
        bh[np * 2][0] = th[0]; bh[np * 2][1] = th[1];
        bh[np * 2 + 1][0] = th[2]; bh[np * 2 + 1][1] = th[3];
        bl[np * 2][0] = tl[0]; bl[np * 2][1] = tl[1];
        bl[np * 2 + 1][0] = tl[2]; bl[np * 2 + 1][1] = tl[3];
      }
#pragma unroll
      for (int mi = 0; mi < 4; mi++)
#pragma unroll
        for (int ni = 0; ni < 8; ni++) {
          mma16816(acc[mi][ni], ah[mi], bh[ni]);
          mma16816(acc[mi][ni], ah[mi], bl[ni]);
          mma16816(acc[mi][ni], al[mi], bh[ni]);
        }
    }
    __syncthreads();
    if (tid == 0 && c + 3 < nc) {
      int cc = c + 3;
      uint32_t bar = sb + st * 16;
      uint32_t d = sb + 1024 + st * STG;
      expect_tx(bar, 49152);
      bulk_ld(d,         Ah + ((size_t)(mblk0 * nK + cc)) * 4096, 8192, bar);
      bulk_ld(d + 8192,  Ah + ((size_t)((mblk0 + 1) * nK + cc)) * 4096, 8192, bar);
      bulk_ld(d + 16384, Al + ((size_t)(mblk0 * nK + cc)) * 4096, 8192, bar);
      bulk_ld(d + 24576, Al + ((size_t)((mblk0 + 1) * nK + cc)) * 4096, 8192, bar);
      bulk_ld(d + 32768, Bh + ((size_t)(nblk * nK + cc)) * 4096, 8192, bar);
      bulk_ld(d + 40960, Bl + ((size_t)(nblk * nK + cc)) * 4096, 8192, bar);
    }
  }

  if (Uh != nullptr) {
    // -------- fused SwiGLU epilogue: interleaved cols (gate,y) pairs ------
    // u = silu(even)*odd -> blocked bf16 hi/lo staged in smem (8 x 8KB tiles:
    // [hi rb0kb0, hi rb0kb1, hi rb1kb0, hi rb1kb1, lo x4]), then coalesced out.
    __syncthreads();
#pragma unroll
    for (int mi = 0; mi < 4; mi++) {
#pragma unroll
      for (int ni = 0; ni < 8; ni++) {
        int jl = wn * 32 + ni * 4 + tig;   // 0..63 local u col
        int kb = jl >> 5, kk = jl & 31;
        int unit = (kk >> 3) & 3;
#pragma unroll
        for (int rr = 0; rr < 2; rr++) {
          int rl = wm * 64 + mi * 16 + gid + rr * 8;  // 0..255
          int rb = rl >> 7, r = rl & 127;
          float gv = acc[mi][ni][rr * 2 + 0];
          float yv = acc[mi][ni][rr * 2 + 1];
          float u = gv / (1.f + expf(-gv)) * yv;
          __nv_bfloat16 h, l;
          split1(u, h, l);
          int su = unit ^ ((r >> 1) & 3);
          uint32_t off = (uint32_t)(rb * 2 + kb) * 8192 + r * 64 + su * 16 +
                         (kk & 7) * 2;
          *(uint16_t*)(sm + 1024 + off) = *(uint16_t*)&h;
          *(uint16_t*)(sm + 1024 + 32768 + off) = *(uint16_t*)&l;
        }
      }
    }
    __syncthreads();
    // copy 64 KB out: 4096 uint4
#pragma unroll
    for (int i = 0; i < 16; i++) {
      int lin = i * 256 + tid;            // 0..4095
      int sel = lin >> 9;                 // 0..7
      int w16 = lin & 511;
      uint4 v = *(uint4*)(sm + 1024 + lin * 16);
      int rb = (sel & 3) >> 1, kb = sel & 1;
      size_t dstb = ((size_t)((blockIdx.y * 2 + rb) * 88 + blockIdx.x * 2 + kb))
                        * 8192 + w16 * 16;
      char* dst = (char*)((sel < 4) ? Uh : Ul) + dstb;
      *(uint4*)dst = v;
    }
    return;
  }

  const int mrow = blockIdx.y * 256 + wm * 64;
  const int ncol = nblk * 128 + wn * 64;
#pragma unroll
  for (int mi = 0; mi < 4; mi++) {
#pragma unroll
    for (int ni = 0; ni < 8; ni++) {
      int r0 = mrow + mi * 16 + gid;
      int cc = ncol + ni * 8 + tig * 2;
      float2 v0 = make_float2(acc[mi][ni][0], acc[mi][ni][1]);
      float2 v1 = make_float2(acc[mi][ni][2], acc[mi][ni][3]);
      if (Res != nullptr) {
        float2 a0 = *reinterpret_cast<const float2*>(Res + (size_t)r0 * N + cc);
        float2 a1 = *reinterpret_cast<const float2*>(Res + (size_t)(r0 + 8) * N + cc);
        v0.x += a0.x; v0.y += a0.y;
        v1.x += a1.x; v1.y += a1.y;
      }
      *reinterpret_cast<float2*>(C + (size_t)r0 * N + cc) = v0;
      *reinterpret_cast<float2*>(C + (size_t)(r0 + 8) * N + cc) = v1;
    }
  }
}

// ---------------------------------------------------------------------------
// Weight transpose + split, vectorized 16B stores. W[K,N] -> blocked [N,K].
// inter=1: interleave Wg cols (gate j -> 2j, y j -> 2j+1).
// grid (N/64, K/64), 256 threads.
// ---------------------------------------------------------------------------
__global__ void __launch_bounds__(256) wsplit_kernel(
    const float* __restrict__ W, __nv_bfloat16* __restrict__ Th,
    __nv_bfloat16* __restrict__ Tl, int K, int N, int nK, int inter) {
  __shared__ float s[64][65];
  int n0 = blockIdx.x * 64, k0 = blockIdx.y * 64;
  int tid = threadIdx.x;
#pragma unroll
  for (int i = 0; i < 4; i++) {
    int li = i * 256 + tid;
    int r = li >> 4;
    int c4 = (li & 15) * 4;
    float4 v = *(const float4*)(W + (size_t)(k0 + r) * N + n0 + c4);
    s[r][c4 + 0] = v.x; s[r][c4 + 1] = v.y;
    s[r][c4 + 2] = v.z; s[r][c4 + 3] = v.w;
  }
  __syncthreads();
#pragma unroll
  for (int it = 0; it < 2; it++) {
    int item = it * 256 + tid;
    int n = item >> 3;
    int oct = item & 7;
    int gn = n0 + n;
    if (inter) gn = (gn < I_) ? (2 * gn) : (2 * (gn - I_) + 1);
    uint32_t hh[4], ll[4];
#pragma unroll
    for (int p = 0; p < 4; p++) {
      __nv_bfloat16 h0, h1, l0, l1;
      split1(s[oct * 8 + 2 * p][n], h0, l0);
      split1(s[oct * 8 + 2 * p + 1][n], h1, l1);
      hh[p] = (uint32_t)*(uint16_t*)&h0 | ((uint32_t)*(uint16_t*)&h1 << 16);
      ll[p] = (uint32_t)*(uint16_t*)&l0 | ((uint32_t)*(uint16_t*)&l1 << 16);
    }
    size_t e = blk_off(gn, k0 + oct * 8, nK);
    *(uint4*)(Th + e) = make_uint4(hh[0], hh[1], hh[2], hh[3]);
    *(uint4*)(Tl + e) = make_uint4(ll[0], ll[1], ll[2], ll[3]);
  }
}

// ---------------------------------------------------------------------------
// RMSNorm per row -> optional fp32 + blocked bf16 hi/lo (nK=32).
// ---------------------------------------------------------------------------
__global__ void __launch_bounds__(256) rmsnorm_split_kernel(
    const float* __restrict__ x, const float* __restrict__ w,
    float* __restrict__ y, __nv_bfloat16* __restrict__ yh,
    __nv_bfloat16* __restrict__ yl) {
  int row = blockIdx.x;
  int tid = threadIdx.x;
  const float4* xr = reinterpret_cast<const float4*>(x + (size_t)row * D_);
  float4 v = xr[tid];
  float ss = v.x * v.x + v.y * v.y + v.z * v.z + v.w * v.w;
#pragma unroll
  for (int o = 16; o > 0; o >>= 1) ss += __shfl_xor_sync(0xffffffffu, ss, o);
  __shared__ float red[8];
  if ((tid & 31) == 0) red[tid >> 5] = ss;
  __syncthreads();
  float tot = red[0] + red[1] + red[2] + red[3] + red[4] + red[5] + red[6] + red[7];
  float r = rsqrtf(tot * (1.0f / 1024.0f) + 1e-6f);
  float4 wv = reinterpret_cast<const float4*>(w)[tid];
  float4 ov = make_float4(v.x * r * wv.x, v.y * r * wv.y,
                          v.z * r * wv.z, v.w * r * wv.w);
  if (y != nullptr)
    reinterpret_cast<float4*>(y + (size_t)row * D_)[tid] = ov;
  __nv_bfloat16 h0, h1, h2, h3, l0, l1, l2, l3;
  split1(ov.x, h0, l0); split1(ov.y, h1, l1);
  split1(ov.z, h2, l2); split1(ov.w, h3, l3);
  size_t e = blk_off(row, tid * 4, 32);
  uint32_t p0 = (uint32_t)*(uint16_t*)&h0 | ((uint32_t)*(uint16_t*)&h1 << 16);
  uint32_t p1 = (uint32_t)*(uint16_t*)&h2 | ((uint32_t)*(uint16_t*)&h3 << 16);
  *reinterpret_cast<uint2*>(yh + e) = make_uint2(p0, p1);
  uint32_t q0 = (uint32_t)*(uint16_t*)&l0 | ((uint32_t)*(uint16_t*)&l1 << 16);
  uint32_t q1 = (uint32_t)*(uint16_t*)&l2 | ((uint32_t)*(uint16_t*)&l3 << 16);
  *reinterpret_cast<uint2*>(yl + e) = make_uint2(q0, q1);
}

// ---------------------------------------------------------------------------
// Fused: causal conv(K=4)+SiLU for q|k|v (from fused qkv [.,3072]) and
// per-64 l2norm for q (scale 1/8) and k. One block per (b,t) row, 384 thr.
// ---------------------------------------------------------------------------
__global__ void __launch_bounds__(384) convnorm_kernel(
    const float* __restrict__ qkv, const float* __restrict__ wq,
    const float* __restrict__ wk, const float* __restrict__ wv,
    float* __restrict__ q, float* __restrict__ k, float* __restrict__ v) {
  int row = blockIdx.x;
  int t = row & 1023;
  int tid = threadIdx.x;
  int c0 = tid * 8;
  int sec = c0 >> 10;           // 0=q 1=k 2=v
  int cl = c0 & 1023;
  const float* w = (sec == 0) ? wq : (sec == 1) ? wk : wv;

  float4 tap[8];
#pragma unroll
  for (int j = 0; j < 8; j++)
    tap[j] = *(const float4*)(w + (cl + j) * 4);

  const float* base = qkv + (size_t)row * 3072 + c0;
  float xr[4][8];
#pragma unroll
  for (int i = 0; i < 4; i++) {
    int tt = t + i - 3;
    if (tt >= 0) {
      float4 a = *(const float4*)(base + (i - 3) * 3072);
      float4 b = *(const float4*)(base + (i - 3) * 3072 + 4);
      xr[i][0] = a.x; xr[i][1] = a.y; xr[i][2] = a.z; xr[i][3] = a.w;
      xr[i][4] = b.x; xr[i][5] = b.y; xr[i][6] = b.z; xr[i][7] = b.w;
    } else {
#pragma unroll
      for (int j = 0; j < 8; j++) xr[i][j] = 0.f;
    }
  }
  float val[8];
  float ss = 0.f;
#pragma unroll
  for (int j = 0; j < 8; j++) {
    float acc = xr[0][j] * tap[j].x + xr[1][j] * tap[j].y +
                xr[2][j] * tap[j].z + xr[3][j] * tap[j].w;
    val[j] = acc / (1.f + expf(-acc));
    ss += val[j] * val[j];
  }
  if (sec < 2) {
    ss += __shfl_xor_sync(0xffffffffu, ss, 1);
    ss += __shfl_xor_sync(0xffffffffu, ss, 2);
    ss += __shfl_xor_sync(0xffffffffu, ss, 4);
    float r = rsqrtf(ss + 1e-6f) * (sec == 0 ? 0.125f : 1.0f);
#pragma unroll
    for (int j = 0; j < 8; j++) val[j] *= r;
  }
  float* dst = ((sec == 0) ? q : (sec == 1) ? k : v) + (size_t)row * 1024 + cl;
  *(float4*)dst = make_float4(val[0], val[1], val[2], val[3]);
  *(float4*)(dst + 4) = make_float4(val[4], val[5], val[6], val[7]);
}

// ---------------------------------------------------------------------------
// Per-64 RMSNorm -> blocked bf16 hi/lo (nK=32).
// ---------------------------------------------------------------------------
__global__ void __launch_bounds__(256) norm64_rms_split_kernel(
    const float* __restrict__ x, const float* __restrict__ w,
    __nv_bfloat16* __restrict__ yh, __nv_bfloat16* __restrict__ yl,
    int ngroups) {
  int gw = (blockIdx.x * blockDim.x + threadIdx.x) >> 5;
  int lane = threadIdx.x & 31;
  if (gw >= ngroups) return;
  const float* p = x + (size_t)gw * 64;
  float a = p[lane];
  float b = p[lane + 32];
  float ss = a * a + b * b;
#pragma unroll
  for (int o = 16; o > 0; o >>= 1) ss += __shfl_xor_sync(0xffffffffu, ss, o);
  float r = rsqrtf(ss * (1.f / 64.f) + 1e-6f);
  a *= r * w[lane];
  b *= r * w[lane + 32];
  int row = gw >> 4;
  int k0 = (gw & 15) * 64;
  __nv_bfloat16 h, l;
  split1(a, h, l);
  size_t e = blk_off(row, k0 + lane, 32);
  yh[e] = h; yl[e] = l;
  split1(b, h, l);
  e = blk_off(row, k0 + lane + 32, 32);
  yh[e] = h; yl[e] = l;
}

// ---------------------------------------------------------------------------
// beta/g gates: block per row.
// ---------------------------------------------------------------------------
__global__ void __launch_bounds__(256) betag_kernel(
    const float* __restrict__ h, const float* __restrict__ Wb,
    const float* __restrict__ Wa, const float* __restrict__ dt_bias,
    const float* __restrict__ A_log, float* __restrict__ beta,
    float* __restrict__ gout) {
  __shared__ float hs[D_];
  __shared__ float pb[256], pa[256];
  int row = blockIdx.x;
  int tid = threadIdx.x;
  reinterpret_cast<float4*>(hs)[tid] =
      reinterpret_cast<const float4*>(h + (size_t)row * D_)[tid];
  __syncthreads();
  int head = tid & 15;
  int chunk = tid >> 4;
  float sb = 0.f, sa = 0.f;
  int base = chunk * 64;
#pragma unroll 8
  for (int i = 0; i < 64; i++) {
    float hv = hs[base + i];
    int wi = (base + i) * 16 + head;
    sb += hv * Wb[wi];
    sa += hv * Wa[wi];
  }
  pb[tid] = sb;
  pa[tid] = sa;
  __syncthreads();
  if (tid < 16) {
    float b = 0.f, a = 0.f;
#pragma unroll
    for (int c = 0; c < 16; c++) {
      b += pb[c * 16 + tid];
      a += pa[c * 16 + tid];
    }
    beta[row * H_ + tid] = 2.f / (1.f + expf(-b));
    float z = a + dt_bias[tid];
    float sp = (z > 20.f) ? z : log1pf(expf(z));
    gout[row * H_ + tid] = -expf(A_log[tid]) * sp;
  }
}

// ---------------------------------------------------------------------------
// Delta-rule scan: 128 blocks (2 per (b,h)), 128 threads.
// ---------------------------------------------------------------------------
__global__ void __launch_bounds__(128) scan_kernel(
    const float* __restrict__ q, const float* __restrict__ k,
    const float* __restrict__ v, const float* __restrict__ beta,
    const float* __restrict__ g, float* __restrict__ o,
    float* __restrict__ state_out) {
  int blk = blockIdx.x;
  int bh = blk >> 1;
  int half = blk & 1;
  int b = bh >> 4, h = bh & 15;
  int tid = threadIdx.x;
  int colL = tid >> 2;
  int col = half * 32 + colL;
  int kq = tid & 3;

  __shared__ float qs[2][64], ks[2][64], vs[2][32], sc[2][2];
  float s[16];
#pragma unroll
  for (int i = 0; i < 16; i++) s[i] = 0.f;

  size_t vecbase = (size_t)b * T_ * 1024 + (size_t)h * 64;
  int bgbase = b * T_ * H_ + h;

  const float* src1 = (tid < 64) ? (q + vecbase + tid) : (k + vecbase + tid - 64);
  const float* src2 = nullptr;
  int str2 = 1024;
  if (tid < 32)        src2 = v + vecbase + half * 32 + tid;
  else if (tid == 32) { src2 = beta + bgbase; str2 = H_; }
  else if (tid == 33) { src2 = g + bgbase;    str2 = H_; }

  float p1 = src1[0];
  float p2 = (src2 != nullptr) ? src2[0] : 0.f;
  int buf = 0;

  for (int t = 0; t < T_; t++) {
    if (tid < 64) qs[buf][tid] = p1;
    else          ks[buf][tid - 64] = p1;
    if (tid < 32)       vs[buf][tid] = p2;
    else if (tid == 32) sc[buf][0] = p2;
    else if (tid == 33) sc[buf][1] = p2;
    __syncthreads();
    if (t + 1 < T_) {
      p1 = src1[(size_t)(t + 1) * 1024];
      if (src2 != nullptr) p2 = src2[(size_t)(t + 1) * str2];
    }

    float eg = expf(sc[buf][1]);
    float bt = sc[buf][0];
    float kk[16], qq[16];
#pragma unroll
    for (int i = 0; i < 16; i++) {
      kk[i] = ks[buf][kq * 16 + i];
      qq[i] = qs[buf][kq * 16 + i];
    }
    float kv0 = 0.f, kv1 = 0.f, qv0 = 0.f, qv1 = 0.f, qk0 = 0.f, qk1 = 0.f;
#pragma unroll
    for (int i = 0; i < 16; i += 2) {
      kv0 += kk[i] * s[i];     kv1 += kk[i + 1] * s[i + 1];
      qv0 += qq[i] * s[i];     qv1 += qq[i + 1] * s[i + 1];
      qk0 += qq[i] * kk[i];    qk1 += qq[i + 1] * kk[i + 1];
    }
    float kv = kv0 + kv1, qv = qv0 + qv1, qk = qk0 + qk1;
    kv += __shfl_xor_sync(0xffffffffu, kv, 1);
    kv += __shfl_xor_sync(0xffffffffu, kv, 2);
    qv += __shfl_xor_sync(0xffffffffu, qv, 1);
    qv += __shfl_xor_sync(0xffffffffu, qv, 2);
    qk += __shfl_xor_sync(0xffffffffu, qk, 1);
    qk += __shfl_xor_sync(0xffffffffu, qk, 2);

    float delta = (vs[buf][colL] - eg * kv) * bt;
#pragma unroll
    for (int i = 0; i < 16; i++) s[i] = eg * s[i] + kk[i] * delta;
    if (kq == 0) o[vecbase + (size_t)t * 1024 + col] = eg * qv + delta * qk;
    buf ^= 1;
  }

  float* sp = state_out + (size_t)bh * 64 * 64;
#pragma unroll
  for (int i = 0; i < 16; i++) sp[(kq * 16 + i) * 64 + col] = s[i];
}

// ---------------------------------------------------------------------------
extern "C" void kernel_launch(void* const* d_in, const int* in_sizes, int n_in,
                              void* d_out, int out_size) {
  const float* x           = (const float*)d_in[0];
  const float* attn_norm_w = (const float*)d_in[1];
  const float* Wq          = (const float*)d_in[2];
  const float* Wk          = (const float*)d_in[3];
  const float* Wv          = (const float*)d_in[4];
  const float* conv_q_w    = (const float*)d_in[5];
  const float* conv_k_w    = (const float*)d_in[6];
  const float* conv_v_w    = (const float*)d_in[7];
  const float* Wb          = (const float*)d_in[8];
  const float* Wa          = (const float*)d_in[9];
  const float* dt_bias     = (const float*)d_in[10];
  const float* A_log       = (const float*)d_in[11];
  const float* o_norm_w    = (const float*)d_in[12];
  const float* Wo          = (const float*)d_in[13];
  const float* mlp_norm_w  = (const float*)d_in[14];
  const float* Wg          = (const float*)d_in[15];
  const float* Wd          = (const float*)d_in[16];
  float* out = (float*)d_out;

  float* pool = nullptr;
  cudaGetSymbolAddress((void**)&pool, g_pool);
  __nv_bfloat16* bf = nullptr;
  cudaGetSymbolAddress((void**)&bf, g_bf);

  cudaFuncSetAttribute(bf16gemm_kernel,
                       cudaFuncAttributeMaxDynamicSharedMemorySize, GEMM_SMEM);

  float* hbuf = pool + OFF_H;
  float* qkvp = pool + OFF_QKV;
  float* qbuf = pool + OFF_Q;
  float* kbuf = pool + OFF_K;
  float* vbuf = pool + OFF_V;
  float* obuf = pool + OFF_O;
  float* h2   = pool + OFF_H2;
  float* bbuf = pool + OFF_BETA;
  float* gbuf = pool + OFF_G;

  dim3 gW64(D_ / 64, D_ / 64);  // (16,16)

  // 0: h = rmsnorm(x) -> fp32 + blocked hi/lo
  rmsnorm_split_kernel<<<ROWS, 256>>>(x, attn_norm_w, hbuf,
                                      bf + BF_AH, bf + BF_AL);
  // 1-3: Wq/Wk/Wv splits
  wsplit_kernel<<<gW64, 256>>>(Wq, bf + BF_WQKVH, bf + BF_WQKVL, D_, D_, 32, 0);
  wsplit_kernel<<<gW64, 256>>>(Wk, bf + BF_WQKVH + W1, bf + BF_WQKVL + W1, D_, D_, 32, 0);
  wsplit_kernel<<<gW64, 256>>>(Wv, bf + BF_WQKVH + 2 * W1, bf + BF_WQKVL + 2 * W1, D_, D_, 32, 0);

  // 4: gates
  betag_kernel<<<ROWS, 256>>>(hbuf, Wb, Wa, dt_bias, A_log, bbuf, gbuf);

  // 5: fused QKV GEMM  (ncu -s 5 profiles this launch)
  bf16gemm_kernel<<<dim3(24, 16), 256, GEMM_SMEM>>>(
      bf + BF_AH, bf + BF_AL, bf + BF_WQKVH, bf + BF_WQKVL,
      nullptr, qkvp, nullptr, nullptr, 3072, 32);

  // other weight splits
  wsplit_kernel<<<gW64, 256>>>(Wo, bf + BF_WOH, bf + BF_WOL, D_, D_, 32, 0);
  wsplit_kernel<<<dim3(TWOI / 64, D_ / 64), 256>>>(Wg, bf + BF_WGH, bf + BF_WGL, D_, TWOI, 32, 1);
  wsplit_kernel<<<dim3(D_ / 64, I_ / 64), 256>>>(Wd, bf + BF_WDH, bf + BF_WDL, I_, D_, 88, 0);

  // conv + SiLU + l2norm (fused)
  convnorm_kernel<<<ROWS, 384>>>(qkvp, conv_q_w, conv_k_w, conv_v_w,
                                 qbuf, kbuf, vbuf);

  // scan
  scan_kernel<<<128, 128>>>(qbuf, kbuf, vbuf, bbuf, gbuf, obuf, out + SZ);

  // per-head RMSNorm -> blocked hi/lo
  int ngrp = ROWS * H_;
  norm64_rms_split_kernel<<<(ngrp * 32) / 256, 256>>>(
      obuf, o_norm_w, bf + BF_OH, bf + BF_OL, ngrp);

  // h2 = o @ Wo + x
  bf16gemm_kernel<<<dim3(8, 16), 256, GEMM_SMEM>>>(
      bf + BF_OH, bf + BF_OL, bf + BF_WOH, bf + BF_WOL, x, h2,
      nullptr, nullptr, 1024, 32);

  // h3 = rmsnorm(h2) -> blocked hi/lo
  rmsnorm_split_kernel<<<ROWS, 256>>>(h2, mlp_norm_w, nullptr,
                                      bf + BF_3H, bf + BF_3L);

  // u = swiglu(h3 @ Wg) -> blocked hi/lo (fused epilogue)
  bf16gemm_kernel<<<dim3(44, 16), 256, GEMM_SMEM>>>(
      bf + BF_3H, bf + BF_3L, bf + BF_WGH, bf + BF_WGL, nullptr, nullptr,
      bf + BF_UH, bf + BF_UL, TWOI, 32);

  // out = u @ Wd + h2
  bf16gemm_kernel<<<dim3(8, 16), 256, GEMM_SMEM>>>(
      bf + BF_UH, bf + BF_UL, bf + BF_WDH, bf + BF_WDL, h2, out,
      nullptr, nullptr, 1024, 88);
}

// round 17
// speedup vs baseline: 1.0220x; 1.0220x over previous
#include <cuda_runtime.h>
#include <cuda_bf16.h>
#include <math.h>
#include <stdint.h>

// ---------------------------------------------------------------------------
// GatedDeltaNet encoder. HMMA bf16 hi/lo GEMMs, blocked-tile layout,
// cp.async.bulk pipeline, fused SwiGLU epilogue, fused conv+l2norm,
// tiled betag, multi-stream overlap of weight splits.
// ---------------------------------------------------------------------------

#define B_    4
#define T_    1024
#define D_    1024
#define H_    16
#define ROWS  (B_ * T_)          // 4096
#define I_    2816
#define TWOI  (2 * I_)           // 5632

static constexpr size_t SZ        = (size_t)ROWS * D_;
static constexpr size_t OFF_H     = 0 * SZ;
static constexpr size_t OFF_QKV   = 1 * SZ;                  // [4096,3072]
static constexpr size_t OFF_Q     = 4 * SZ;
static constexpr size_t OFF_K     = 5 * SZ;
static constexpr size_t OFF_V     = 6 * SZ;
static constexpr size_t OFF_O     = 7 * SZ;
static constexpr size_t OFF_H2    = 8 * SZ;
static constexpr size_t OFF_BETA  = 9 * SZ;
static constexpr size_t OFF_G     = OFF_BETA + (size_t)ROWS * H_;
static constexpr size_t POOL_SZ   = OFF_G + (size_t)ROWS * H_;

static __device__ __align__(256) float g_pool[POOL_SZ];

static constexpr size_t S1  = (size_t)ROWS * D_;
static constexpr size_t S2  = (size_t)ROWS * I_;
static constexpr size_t W1  = (size_t)D_ * D_;
static constexpr size_t SWG = (size_t)TWOI * D_;
static constexpr size_t SWD = (size_t)D_ * I_;

static constexpr size_t BF_AH  = 0;
static constexpr size_t BF_AL  = 1 * S1;
static constexpr size_t BF_OH  = 2 * S1;
static constexpr size_t BF_OL  = 3 * S1;
static constexpr size_t BF_3H  = 4 * S1;
static constexpr size_t BF_3L  = 5 * S1;
static constexpr size_t BF_UH  = 6 * S1;
static constexpr size_t BF_UL  = 6 * S1 + S2;
static constexpr size_t BF_WQKVH = 6 * S1 + 2 * S2;
static constexpr size_t BF_WQKVL = BF_WQKVH + 3 * W1;
static constexpr size_t BF_WOH = BF_WQKVL + 3 * W1;
static constexpr size_t BF_WOL = BF_WOH + W1;
static constexpr size_t BF_WGH = BF_WOL + W1;
static constexpr size_t BF_WGL = BF_WGH + SWG;
static constexpr size_t BF_WDH = BF_WGL + SWG;
static constexpr size_t BF_WDL = BF_WDH + SWD;
static constexpr size_t BF_SZ  = BF_WDL + SWD;

static __device__ __align__(256) __nv_bfloat16 g_bf[BF_SZ];

// ---------------------------------------------------------------------------
__device__ __forceinline__ uint32_t smem_u32(const void* p) {
  uint32_t r;
  asm("{ .reg .u64 t; cvta.to.shared.u64 t, %1; cvt.u32.u64 %0, t; }"
      : "=r"(r) : "l"(p));
  return r;
}
__device__ __forceinline__ void mbar_init(uint32_t a, uint32_t c) {
  asm volatile("mbarrier.init.shared.b64 [%0], %1;" :: "r"(a), "r"(c) : "memory");
}
__device__ __forceinline__ void mbar_wait(uint32_t a, uint32_t par) {
  asm volatile(
      "{\n\t.reg .pred P;\n"
      "W%=:\n\tmbarrier.try_wait.parity.acquire.cta.shared::cta.b64 P, [%0], %1, 0x989680;\n"
      "\t@!P bra W%=;\n\t}"
      :: "r"(a), "r"(par) : "memory");
}
__device__ __forceinline__ void expect_tx(uint32_t bar, uint32_t bytes) {
  asm volatile("mbarrier.arrive.expect_tx.shared.b64 _, [%0], %1;"
               :: "r"(bar), "r"(bytes) : "memory");
}
__device__ __forceinline__ void bulk_ld(uint32_t dst, const void* src,
                                        uint32_t bytes, uint32_t bar) {
  asm volatile(
      "cp.async.bulk.shared::cluster.global.mbarrier::complete_tx::bytes "
      "[%0], [%1], %2, [%3];"
      :: "r"(dst), "l"(src), "r"(bytes), "r"(bar) : "memory");
}
__device__ __forceinline__ void ldsm4(uint32_t* r, uint32_t addr) {
  asm volatile(
      "ldmatrix.sync.aligned.m8n8.x4.shared.b16 {%0,%1,%2,%3}, [%4];"
      : "=r"(r[0]), "=r"(r[1]), "=r"(r[2]), "=r"(r[3])
      : "r"(addr));
}
__device__ __forceinline__ void mma16816(float* d, const uint32_t* a,
                                         const uint32_t* b) {
  asm volatile(
      "mma.sync.aligned.m16n8k16.row.col.f32.bf16.bf16.f32 "
      "{%0,%1,%2,%3}, {%4,%5,%6,%7}, {%8,%9}, {%0,%1,%2,%3};"
      : "+f"(d[0]), "+f"(d[1]), "+f"(d[2]), "+f"(d[3])
      : "r"(a[0]), "r"(a[1]), "r"(a[2]), "r"(a[3]), "r"(b[0]), "r"(b[1]));
}
__device__ __forceinline__ void split1(float v, __nv_bfloat16& h,
                                       __nv_bfloat16& l) {
  h = __float2bfloat16_rn(v);
  l = __float2bfloat16_rn(v - __bfloat162float(h));
}

// Blocked layout: [N/128][K/32] tiles of 128x32 bf16 (8192 B); rows 64 B;
// 16B units swizzled u ^= (r>>1)&3.
__device__ __forceinline__ size_t blk_off(int n, int k, int nK) {
  int nb = n >> 7, r = n & 127, kb = k >> 5;
  int unit = (k >> 3) & 3;
  int su = unit ^ ((r >> 1) & 3);
  size_t byte = ((size_t)(nb * nK + kb)) * 8192 + r * 64 + su * 16 + (k & 7) * 2;
  return byte >> 1;
}

// ---------------------------------------------------------------------------
// GEMM: C = (Ah+Al)(Bh+Bl)^T (+Res), or fused SwiGLU epilogue -> Uh/Ul.
// CTA 256x128, BK=32, 3 stages. 8 warps (4m x 2n), warp tile 64x64.
// ---------------------------------------------------------------------------
static constexpr int STG = 49152;
static constexpr int GEMM_SMEM = 1024 + 3 * STG;  // 148480

__global__ void __launch_bounds__(256, 1)
bf16gemm_kernel(const __nv_bfloat16* __restrict__ Ah,
                const __nv_bfloat16* __restrict__ Al,
                const __nv_bfloat16* __restrict__ Bh,
                const __nv_bfloat16* __restrict__ Bl,
                const float* __restrict__ Res, float* __restrict__ C,
                __nv_bfloat16* __restrict__ Uh, __nv_bfloat16* __restrict__ Ul,
                int N, int nK) {
  extern __shared__ __align__(16) char sm[];
  uint32_t sb = smem_u32(sm);
  const int tid = threadIdx.x;
  const int wid = tid >> 5, lid = tid & 31;
  const int gid = lid >> 2, tig = lid & 3;
  const int sub = lid >> 3, r8 = lid & 7;
  const int wm = wid >> 1, wn = wid & 1;
  const int mblk0 = blockIdx.y * 2;
  const int nblk = blockIdx.x;
  const int nc = nK;
  const int sx = (r8 >> 1) & 3;

  if (tid == 0) {
    mbar_init(sb + 0, 1);
    mbar_init(sb + 16, 1);
    mbar_init(sb + 32, 1);
  }
  __syncthreads();

  float acc[4][8][4];
#pragma unroll
  for (int i = 0; i < 4; i++)
#pragma unroll
    for (int j = 0; j < 8; j++)
#pragma unroll
      for (int r = 0; r < 4; r++) acc[i][j][r] = 0.f;

  if (tid == 0) {
#pragma unroll
    for (int s = 0; s < 3; s++) {
      uint32_t bar = sb + s * 16;
      uint32_t d = sb + 1024 + s * STG;
      expect_tx(bar, 49152);
      bulk_ld(d,         Ah + ((size_t)(mblk0 * nK + s)) * 4096, 8192, bar);
      bulk_ld(d + 8192,  Ah + ((size_t)((mblk0 + 1) * nK + s)) * 4096, 8192, bar);
      bulk_ld(d + 16384, Al + ((size_t)(mblk0 * nK + s)) * 4096, 8192, bar);
      bulk_ld(d + 24576, Al + ((size_t)((mblk0 + 1) * nK + s)) * 4096, 8192, bar);
      bulk_ld(d + 32768, Bh + ((size_t)(nblk * nK + s)) * 4096, 8192, bar);
      bulk_ld(d + 40960, Bl + ((size_t)(nblk * nK + s)) * 4096, 8192, bar);
    }
  }

  const uint32_t aRow = (uint32_t)((wm & 1) * 64 + (sub & 1) * 8 + r8) * 64;
  const uint32_t aTile = (uint32_t)(wm >> 1) * 8192;
  const uint32_t bRow = (uint32_t)(wn * 64 + (sub >> 1) * 8 + r8) * 64;

  for (int c = 0; c < nc; c++) {
    int st = c % 3;
    mbar_wait(sb + st * 16, (c / 3) & 1);

    uint32_t stage = sb + 1024 + st * STG;
    uint32_t aB = stage + aTile + aRow;
    uint32_t bB = stage + 32768 + bRow;
#pragma unroll
    for (int ks = 0; ks < 2; ks++) {
      uint32_t ua = (uint32_t)((ks * 2 + (sub >> 1)) ^ sx) << 4;
      uint32_t ub = (uint32_t)((ks * 2 + (sub & 1)) ^ sx) << 4;
      uint32_t ah[4][4], al[4][4], bh[8][2], bl[8][2];
#pragma unroll
      for (int mi = 0; mi < 4; mi++) {
        uint32_t ad = aB + mi * 1024 + ua;
        ldsm4(ah[mi], ad);
        ldsm4(al[mi], ad + 16384);
      }
#pragma unroll
      for (int np = 0; np < 4; np++) {
        uint32_t bd = bB + np * 1024 + ub;
        uint32_t th[4], tl[4];
        ldsm4(th, bd);
        ldsm4(tl, bd + 8192);
        bh[np * 2][0] = th[0]; bh[np * 2][1] = th[1];
        bh[np * 2 + 1][0] = th[2]; bh[np * 2 + 1][1] = th[3];
        bl[np * 2][0] = tl[0]; bl[np * 2][1] = tl[1];
        bl[np * 2 + 1][0] = tl[2]; bl[np * 2 + 1][1] = tl[3];
      }
#pragma unroll
      for (int mi = 0; mi < 4; mi++)
#pragma unroll
        for (int ni = 0; ni < 8; ni++) {
          mma16816(acc[mi][ni], ah[mi], bh[ni]);
          mma16816(acc[mi][ni], ah[mi], bl[ni]);
          mma16816(acc[mi][ni], al[mi], bh[ni]);
        }
    }
    __syncthreads();
    if (tid == 0 && c + 3 < nc) {
      int cc = c + 3;
      uint32_t bar = sb + st * 16;
      uint32_t d = sb + 1024 + st * STG;
      expect_tx(bar, 49152);
      bulk_ld(d,         Ah + ((size_t)(mblk0 * nK + cc)) * 4096, 8192, bar);
      bulk_ld(d + 8192,  Ah + ((size_t)((mblk0 + 1) * nK + cc)) * 4096, 8192, bar);
      bulk_ld(d + 16384, Al + ((size_t)(mblk0 * nK + cc)) * 4096, 8192, bar);
      bulk_ld(d + 24576, Al + ((size_t)((mblk0 + 1) * nK + cc)) * 4096, 8192, bar);
      bulk_ld(d + 32768, Bh + ((size_t)(nblk * nK + cc)) * 4096, 8192, bar);
      bulk_ld(d + 40960, Bl + ((size_t)(nblk * nK + cc)) * 4096, 8192, bar);
    }
  }

  if (Uh != nullptr) {
    // fused SwiGLU epilogue: interleaved cols -> (gate,y) pairs in acc.
    __syncthreads();
#pragma unroll
    for (int mi = 0; mi < 4; mi++) {
#pragma unroll
      for (int ni = 0; ni < 8; ni++) {
        int jl = wn * 32 + ni * 4 + tig;
        int kb = jl >> 5, kk = jl & 31;
        int unit = (kk >> 3) & 3;
#pragma unroll
        for (int rr = 0; rr < 2; rr++) {
          int rl = wm * 64 + mi * 16 + gid + rr * 8;
          int rb = rl >> 7, r = rl & 127;
          float gv = acc[mi][ni][rr * 2 + 0];
          float yv = acc[mi][ni][rr * 2 + 1];
          float u = gv / (1.f + expf(-gv)) * yv;
          __nv_bfloat16 h, l;
          split1(u, h, l);
          int su = unit ^ ((r >> 1) & 3);
          uint32_t off = (uint32_t)(rb * 2 + kb) * 8192 + r * 64 + su * 16 +
                         (kk & 7) * 2;
          *(uint16_t*)(sm + 1024 + off) = *(uint16_t*)&h;
          *(uint16_t*)(sm + 1024 + 32768 + off) = *(uint16_t*)&l;
        }
      }
    }
    __syncthreads();
#pragma unroll
    for (int i = 0; i < 16; i++) {
      int lin = i * 256 + tid;
      int sel = lin >> 9;
      int w16 = lin & 511;
      uint4 v = *(uint4*)(sm + 1024 + lin * 16);
      int rb = (sel & 3) >> 1, kb = sel & 1;
      size_t dstb = ((size_t)((blockIdx.y * 2 + rb) * 88 + blockIdx.x * 2 + kb))
                        * 8192 + w16 * 16;
      char* dst = (char*)((sel < 4) ? Uh : Ul) + dstb;
      *(uint4*)dst = v;
    }
    return;
  }

  const int mrow = blockIdx.y * 256 + wm * 64;
  const int ncol = nblk * 128 + wn * 64;
#pragma unroll
  for (int mi = 0; mi < 4; mi++) {
#pragma unroll
    for (int ni = 0; ni < 8; ni++) {
      int r0 = mrow + mi * 16 + gid;
      int cc = ncol + ni * 8 + tig * 2;
      float2 v0 = make_float2(acc[mi][ni][0], acc[mi][ni][1]);
      float2 v1 = make_float2(acc[mi][ni][2], acc[mi][ni][3]);
      if (Res != nullptr) {
        float2 a0 = *reinterpret_cast<const float2*>(Res + (size_t)r0 * N + cc);
        float2 a1 = *reinterpret_cast<const float2*>(Res + (size_t)(r0 + 8) * N + cc);
        v0.x += a0.x; v0.y += a0.y;
        v1.x += a1.x; v1.y += a1.y;
      }
      *reinterpret_cast<float2*>(C + (size_t)r0 * N + cc) = v0;
      *reinterpret_cast<float2*>(C + (size_t)(r0 + 8) * N + cc) = v1;
    }
  }
}

// ---------------------------------------------------------------------------
// Weight transpose + split, vectorized 16B stores. W[K,N] -> blocked [N,K].
// inter=1: interleave Wg cols (gate j -> 2j, y j -> 2j+1).
// ---------------------------------------------------------------------------
__global__ void __launch_bounds__(256) wsplit_kernel(
    const float* __restrict__ W, __nv_bfloat16* __restrict__ Th,
    __nv_bfloat16* __restrict__ Tl, int K, int N, int nK, int inter) {
  __shared__ float s[64][65];
  int n0 = blockIdx.x * 64, k0 = blockIdx.y * 64;
  int tid = threadIdx.x;
#pragma unroll
  for (int i = 0; i < 4; i++) {
    int li = i * 256 + tid;
    int r = li >> 4;
    int c4 = (li & 15) * 4;
    float4 v = *(const float4*)(W + (size_t)(k0 + r) * N + n0 + c4);
    s[r][c4 + 0] = v.x; s[r][c4 + 1] = v.y;
    s[r][c4 + 2] = v.z; s[r][c4 + 3] = v.w;
  }
  __syncthreads();
#pragma unroll
  for (int it = 0; it < 2; it++) {
    int item = it * 256 + tid;
    int n = item >> 3;
    int oct = item & 7;
    int gn = n0 + n;
    if (inter) gn = (gn < I_) ? (2 * gn) : (2 * (gn - I_) + 1);
    uint32_t hh[4], ll[4];
#pragma unroll
    for (int p = 0; p < 4; p++) {
      __nv_bfloat16 h0, h1, l0, l1;
      split1(s[oct * 8 + 2 * p][n], h0, l0);
      split1(s[oct * 8 + 2 * p + 1][n], h1, l1);
      hh[p] = (uint32_t)*(uint16_t*)&h0 | ((uint32_t)*(uint16_t*)&h1 << 16);
      ll[p] = (uint32_t)*(uint16_t*)&l0 | ((uint32_t)*(uint16_t*)&l1 << 16);
    }
    size_t e = blk_off(gn, k0 + oct * 8, nK);
    *(uint4*)(Th + e) = make_uint4(hh[0], hh[1], hh[2], hh[3]);
    *(uint4*)(Tl + e) = make_uint4(ll[0], ll[1], ll[2], ll[3]);
  }
}

// ---------------------------------------------------------------------------
// RMSNorm per row -> optional fp32 + blocked bf16 hi/lo (nK=32).
// ---------------------------------------------------------------------------
__global__ void __launch_bounds__(256) rmsnorm_split_kernel(
    const float* __restrict__ x, const float* __restrict__ w,
    float* __restrict__ y, __nv_bfloat16* __restrict__ yh,
    __nv_bfloat16* __restrict__ yl) {
  int row = blockIdx.x;
  int tid = threadIdx.x;
  const float4* xr = reinterpret_cast<const float4*>(x + (size_t)row * D_);
  float4 v = xr[tid];
  float ss = v.x * v.x + v.y * v.y + v.z * v.z + v.w * v.w;
#pragma unroll
  for (int o = 16; o > 0; o >>= 1) ss += __shfl_xor_sync(0xffffffffu, ss, o);
  __shared__ float red[8];
  if ((tid & 31) == 0) red[tid >> 5] = ss;
  __syncthreads();
  float tot = red[0] + red[1] + red[2] + red[3] + red[4] + red[5] + red[6] + red[7];
  float r = rsqrtf(tot * (1.0f / 1024.0f) + 1e-6f);
  float4 wv = reinterpret_cast<const float4*>(w)[tid];
  float4 ov = make_float4(v.x * r * wv.x, v.y * r * wv.y,
                          v.z * r * wv.z, v.w * r * wv.w);
  if (y != nullptr)
    reinterpret_cast<float4*>(y + (size_t)row * D_)[tid] = ov;
  __nv_bfloat16 h0, h1, h2, h3, l0, l1, l2, l3;
  split1(ov.x, h0, l0); split1(ov.y, h1, l1);
  split1(ov.z, h2, l2); split1(ov.w, h3, l3);
  size_t e = blk_off(row, tid * 4, 32);
  uint32_t p0 = (uint32_t)*(uint16_t*)&h0 | ((uint32_t)*(uint16_t*)&h1 << 16);
  uint32_t p1 = (uint32_t)*(uint16_t*)&h2 | ((uint32_t)*(uint16_t*)&h3 << 16);
  *reinterpret_cast<uint2*>(yh + e) = make_uint2(p0, p1);
  uint32_t q0 = (uint32_t)*(uint16_t*)&l0 | ((uint32_t)*(uint16_t*)&l1 << 16);
  uint32_t q1 = (uint32_t)*(uint16_t*)&l2 | ((uint32_t)*(uint16_t*)&l3 << 16);
  *reinterpret_cast<uint2*>(yl + e) = make_uint2(q0, q1);
}

// ---------------------------------------------------------------------------
// Fused: causal conv(K=4)+SiLU for q|k|v + per-64 l2norm for q,k.
// One block per (b,t) row, 384 threads.
// ---------------------------------------------------------------------------
__global__ void __launch_bounds__(384) convnorm_kernel(
    const float* __restrict__ qkv, const float* __restrict__ wq,
    const float* __restrict__ wk, const float* __restrict__ wv,
    float* __restrict__ q, float* __restrict__ k, float* __restrict__ v) {
  int row = blockIdx.x;
  int t = row & 1023;
  int tid = threadIdx.x;
  int c0 = tid * 8;
  int sec = c0 >> 10;
  int cl = c0 & 1023;
  const float* w = (sec == 0) ? wq : (sec == 1) ? wk : wv;

  float4 tap[8];
#pragma unroll
  for (int j = 0; j < 8; j++)
    tap[j] = *(const float4*)(w + (cl + j) * 4);

  const float* base = qkv + (size_t)row * 3072 + c0;
  float xr[4][8];
#pragma unroll
  for (int i = 0; i < 4; i++) {
    int tt = t + i - 3;
    if (tt >= 0) {
      float4 a = *(const float4*)(base + (i - 3) * 3072);
      float4 b = *(const float4*)(base + (i - 3) * 3072 + 4);
      xr[i][0] = a.x; xr[i][1] = a.y; xr[i][2] = a.z; xr[i][3] = a.w;
      xr[i][4] = b.x; xr[i][5] = b.y; xr[i][6] = b.z; xr[i][7] = b.w;
    } else {
#pragma unroll
      for (int j = 0; j < 8; j++) xr[i][j] = 0.f;
    }
  }
  float val[8];
  float ss = 0.f;
#pragma unroll
  for (int j = 0; j < 8; j++) {
    float acc = xr[0][j] * tap[j].x + xr[1][j] * tap[j].y +
                xr[2][j] * tap[j].z + xr[3][j] * tap[j].w;
    val[j] = acc / (1.f + expf(-acc));
    ss += val[j] * val[j];
  }
  if (sec < 2) {
    ss += __shfl_xor_sync(0xffffffffu, ss, 1);
    ss += __shfl_xor_sync(0xffffffffu, ss, 2);
    ss += __shfl_xor_sync(0xffffffffu, ss, 4);
    float r = rsqrtf(ss + 1e-6f) * (sec == 0 ? 0.125f : 1.0f);
#pragma unroll
    for (int j = 0; j < 8; j++) val[j] *= r;
  }
  float* dst = ((sec == 0) ? q : (sec == 1) ? k : v) + (size_t)row * 1024 + cl;
  *(float4*)dst = make_float4(val[0], val[1], val[2], val[3]);
  *(float4*)(dst + 4) = make_float4(val[4], val[5], val[6], val[7]);
}

// ---------------------------------------------------------------------------
// Per-64 RMSNorm -> blocked bf16 hi/lo (nK=32).
// ---------------------------------------------------------------------------
__global__ void __launch_bounds__(256) norm64_rms_split_kernel(
    const float* __restrict__ x, const float* __restrict__ w,
    __nv_bfloat16* __restrict__ yh, __nv_bfloat16* __restrict__ yl,
    int ngroups) {
  int gw = (blockIdx.x * blockDim.x + threadIdx.x) >> 5;
  int lane = threadIdx.x & 31;
  if (gw >= ngroups) return;
  const float* p = x + (size_t)gw * 64;
  float a = p[lane];
  float b = p[lane + 32];
  float ss = a * a + b * b;
#pragma unroll
  for (int o = 16; o > 0; o >>= 1) ss += __shfl_xor_sync(0xffffffffu, ss, o);
  float r = rsqrtf(ss * (1.f / 64.f) + 1e-6f);
  a *= r * w[lane];
  b *= r * w[lane + 32];
  int row = gw >> 4;
  int k0 = (gw & 15) * 64;
  __nv_bfloat16 h, l;
  split1(a, h, l);
  size_t e = blk_off(row, k0 + lane, 32);
  yh[e] = h; yl[e] = l;
  split1(b, h, l);
  e = blk_off(row, k0 + lane + 32, 32);
  yh[e] = h; yl[e] = l;
}

// ---------------------------------------------------------------------------
// beta/g gates: 16 rows per block, h staged in 64KB dyn smem, weights
// reused 16x from registers. 256 blocks, 256 threads, 98304 B dyn smem.
// ---------------------------------------------------------------------------
__global__ void __launch_bounds__(256) betag_kernel(
    const float* __restrict__ h, const float* __restrict__ Wb,
    const float* __restrict__ Wa, const float* __restrict__ dt_bias,
    const float* __restrict__ A_log, float* __restrict__ beta,
    float* __restrict__ gout) {
  extern __shared__ float dsm[];
  float* hs = dsm;              // [16][1024]
  float* pb = dsm + 16384;      // [2][16][256]  layout kc*256 + r*16 + head
  float* pa = dsm + 16384 + 4096;
  int row0 = blockIdx.x * 16;
  int tid = threadIdx.x;
  const float4* src = (const float4*)(h + (size_t)row0 * D_);
  float4* d4 = (float4*)hs;
  for (int i = tid; i < 4096; i += 256) d4[i] = src[i];
  __syncthreads();
  int head = tid & 15;
  int kc = tid >> 4;   // 0..15, 64 k each
  float aB[16], aA[16];
#pragma unroll
  for (int r = 0; r < 16; r++) { aB[r] = 0.f; aA[r] = 0.f; }
  int k0 = kc * 64;
  for (int j = 0; j < 64; j++) {
    int kk = k0 + j;
    float wb = Wb[kk * 16 + head];
    float wa = Wa[kk * 16 + head];
#pragma unroll
    for (int r = 0; r < 16; r++) {
      float hv = hs[r * 1024 + kk];
      aB[r] += hv * wb;
      aA[r] += hv * wa;
    }
  }
#pragma unroll
  for (int r = 0; r < 16; r++) {
    pb[kc * 256 + r * 16 + head] = aB[r];
    pa[kc * 256 + r * 16 + head] = aA[r];
  }
  __syncthreads();
  int r = tid >> 4, hd = tid & 15;
  float sb = 0.f, sa = 0.f;
#pragma unroll
  for (int c = 0; c < 16; c++) {
    sb += pb[c * 256 + tid];
    sa += pa[c * 256 + tid];
  }
  beta[(row0 + r) * H_ + hd] = 2.f / (1.f + expf(-sb));
  float z = sa + dt_bias[hd];
  float sp = (z > 20.f) ? z : log1pf(expf(z));
  gout[(row0 + r) * H_ + hd] = -expf(A_log[hd]) * sp;
}

// ---------------------------------------------------------------------------
// Delta-rule scan: 128 blocks (2 per (b,h)), 128 threads.
// ---------------------------------------------------------------------------
__global__ void __launch_bounds__(128) scan_kernel(
    const float* __restrict__ q, const float* __restrict__ k,
    const float* __restrict__ v, const float* __restrict__ beta,
    const float* __restrict__ g, float* __restrict__ o,
    float* __restrict__ state_out) {
  int blk = blockIdx.x;
  int bh = blk >> 1;
  int half = blk & 1;
  int b = bh >> 4, h = bh & 15;
  int tid = threadIdx.x;
  int colL = tid >> 2;
  int col = half * 32 + colL;
  int kq = tid & 3;

  __shared__ float qs[2][64], ks[2][64], vs[2][32], sc[2][2];
  float s[16];
#pragma unroll
  for (int i = 0; i < 16; i++) s[i] = 0.f;

  size_t vecbase = (size_t)b * T_ * 1024 + (size_t)h * 64;
  int bgbase = b * T_ * H_ + h;

  const float* src1 = (tid < 64) ? (q + vecbase + tid) : (k + vecbase + tid - 64);
  const float* src2 = nullptr;
  int str2 = 1024;
  if (tid < 32)        src2 = v + vecbase + half * 32 + tid;
  else if (tid == 32) { src2 = beta + bgbase; str2 = H_; }
  else if (tid == 33) { src2 = g + bgbase;    str2 = H_; }

  float p1 = src1[0];
  float p2 = (src2 != nullptr) ? src2[0] : 0.f;
  int buf = 0;

  for (int t = 0; t < T_; t++) {
    if (tid < 64) qs[buf][tid] = p1;
    else          ks[buf][tid - 64] = p1;
    if (tid < 32)       vs[buf][tid] = p2;
    else if (tid == 32) sc[buf][0] = p2;
    else if (tid == 33) sc[buf][1] = p2;
    __syncthreads();
    if (t + 1 < T_) {
      p1 = src1[(size_t)(t + 1) * 1024];
      if (src2 != nullptr) p2 = src2[(size_t)(t + 1) * str2];
    }

    float eg = expf(sc[buf][1]);
    float bt = sc[buf][0];
    float kk[16], qq[16];
#pragma unroll
    for (int i = 0; i < 16; i++) {
      kk[i] = ks[buf][kq * 16 + i];
      qq[i] = qs[buf][kq * 16 + i];
    }
    float kv0 = 0.f, kv1 = 0.f, qv0 = 0.f, qv1 = 0.f, qk0 = 0.f, qk1 = 0.f;
#pragma unroll
    for (int i = 0; i < 16; i += 2) {
      kv0 += kk[i] * s[i];     kv1 += kk[i + 1] * s[i + 1];
      qv0 += qq[i] * s[i];     qv1 += qq[i + 1] * s[i + 1];
      qk0 += qq[i] * kk[i];    qk1 += qq[i + 1] * kk[i + 1];
    }
    float kv = kv0 + kv1, qv = qv0 + qv1, qk = qk0 + qk1;
    kv += __shfl_xor_sync(0xffffffffu, kv, 1);
    kv += __shfl_xor_sync(0xffffffffu, kv, 2);
    qv += __shfl_xor_sync(0xffffffffu, qv, 1);
    qv += __shfl_xor_sync(0xffffffffu, qv, 2);
    qk += __shfl_xor_sync(0xffffffffu, qk, 1);
    qk += __shfl_xor_sync(0xffffffffu, qk, 2);

    float delta = (vs[buf][colL] - eg * kv) * bt;
#pragma unroll
    for (int i = 0; i < 16; i++) s[i] = eg * s[i] + kk[i] * delta;
    if (kq == 0) o[vecbase + (size_t)t * 1024 + col] = eg * qv + delta * qk;
    buf ^= 1;
  }

  float* sp = state_out + (size_t)bh * 64 * 64;
#pragma unroll
  for (int i = 0; i < 16; i++) sp[(kq * 16 + i) * 64 + col] = s[i];
}

// ---------------------------------------------------------------------------
extern "C" void kernel_launch(void* const* d_in, const int* in_sizes, int n_in,
                              void* d_out, int out_size) {
  const float* x           = (const float*)d_in[0];
  const float* attn_norm_w = (const float*)d_in[1];
  const float* Wq          = (const float*)d_in[2];
  const float* Wk          = (const float*)d_in[3];
  const float* Wv          = (const float*)d_in[4];
  const float* conv_q_w    = (const float*)d_in[5];
  const float* conv_k_w    = (const float*)d_in[6];
  const float* conv_v_w    = (const float*)d_in[7];
  const float* Wb          = (const float*)d_in[8];
  const float* Wa          = (const float*)d_in[9];
  const float* dt_bias     = (const float*)d_in[10];
  const float* A_log       = (const float*)d_in[11];
  const float* o_norm_w    = (const float*)d_in[12];
  const float* Wo          = (const float*)d_in[13];
  const float* mlp_norm_w  = (const float*)d_in[14];
  const float* Wg          = (const float*)d_in[15];
  const float* Wd          = (const float*)d_in[16];
  float* out = (float*)d_out;

  float* pool = nullptr;
  cudaGetSymbolAddress((void**)&pool, g_pool);
  __nv_bfloat16* bf = nullptr;
  cudaGetSymbolAddress((void**)&bf, g_bf);

  cudaFuncSetAttribute(bf16gemm_kernel,
                       cudaFuncAttributeMaxDynamicSharedMemorySize, GEMM_SMEM);
  cudaFuncSetAttribute(betag_kernel,
                       cudaFuncAttributeMaxDynamicSharedMemorySize, 98304);

  // one-time host-side stream/event setup (no device allocations)
  static cudaStream_t sA = nullptr;
  static cudaEvent_t eF = nullptr, e1 = nullptr, e2 = nullptr;
  if (sA == nullptr) {
    cudaStreamCreateWithFlags(&sA, cudaStreamNonBlocking);
    cudaEventCreateWithFlags(&eF, cudaEventDisableTiming);
    cudaEventCreateWithFlags(&e1, cudaEventDisableTiming);
    cudaEventCreateWithFlags(&e2, cudaEventDisableTiming);
  }

  float* hbuf = pool + OFF_H;
  float* qkvp = pool + OFF_QKV;
  float* qbuf = pool + OFF_Q;
  float* kbuf = pool + OFF_K;
  float* vbuf = pool + OFF_V;
  float* obuf = pool + OFF_O;
  float* h2   = pool + OFF_H2;
  float* bbuf = pool + OFF_BETA;
  float* gbuf = pool + OFF_G;

  cudaStream_t m = (cudaStream_t)0;
  dim3 gW64(D_ / 64, D_ / 64);

  // fork side stream for all weight splits
  cudaEventRecord(eF, m);
  cudaStreamWaitEvent(sA, eF, 0);
  wsplit_kernel<<<gW64, 256, 0, sA>>>(Wq, bf + BF_WQKVH, bf + BF_WQKVL, D_, D_, 32, 0);
  wsplit_kernel<<<gW64, 256, 0, sA>>>(Wk, bf + BF_WQKVH + W1, bf + BF_WQKVL + W1, D_, D_, 32, 0);
  wsplit_kernel<<<gW64, 256, 0, sA>>>(Wv, bf + BF_WQKVH + 2 * W1, bf + BF_WQKVL + 2 * W1, D_, D_, 32, 0);
  cudaEventRecord(e1, sA);
  wsplit_kernel<<<gW64, 256, 0, sA>>>(Wo, bf + BF_WOH, bf + BF_WOL, D_, D_, 32, 0);
  wsplit_kernel<<<dim3(TWOI / 64, D_ / 64), 256, 0, sA>>>(Wg, bf + BF_WGH, bf + BF_WGL, D_, TWOI, 32, 1);
  wsplit_kernel<<<dim3(D_ / 64, I_ / 64), 256, 0, sA>>>(Wd, bf + BF_WDH, bf + BF_WDL, I_, D_, 88, 0);
  cudaEventRecord(e2, sA);

  // main stream: h = rmsnorm(x), gates
  rmsnorm_split_kernel<<<ROWS, 256, 0, m>>>(x, attn_norm_w, hbuf,
                                            bf + BF_AH, bf + BF_AL);
  betag_kernel<<<ROWS / 16, 256, 98304, m>>>(hbuf, Wb, Wa, dt_bias, A_log,
                                             bbuf, gbuf);

  // QKV GEMM (needs Wqkv splits)
  cudaStreamWaitEvent(m, e1, 0);
  bf16gemm_kernel<<<dim3(24, 16), 256, GEMM_SMEM, m>>>(
      bf + BF_AH, bf + BF_AL, bf + BF_WQKVH, bf + BF_WQKVL,
      nullptr, qkvp, nullptr, nullptr, 3072, 32);

  // conv + SiLU + l2norm
  convnorm_kernel<<<ROWS, 384, 0, m>>>(qkvp, conv_q_w, conv_k_w, conv_v_w,
                                       qbuf, kbuf, vbuf);

  // scan
  scan_kernel<<<128, 128, 0, m>>>(qbuf, kbuf, vbuf, bbuf, gbuf, obuf, out + SZ);

  // per-head RMSNorm -> blocked hi/lo
  int ngrp = ROWS * H_;
  norm64_rms_split_kernel<<<(ngrp * 32) / 256, 256, 0, m>>>(
      obuf, o_norm_w, bf + BF_OH, bf + BF_OL, ngrp);

  // h2 = o @ Wo + x  (needs remaining weight splits)
  cudaStreamWaitEvent(m, e2, 0);
  bf16gemm_kernel<<<dim3(8, 16), 256, GEMM_SMEM, m>>>(
      bf + BF_OH, bf + BF_OL, bf + BF_WOH, bf + BF_WOL, x, h2,
      nullptr, nullptr, 1024, 32);

  // h3 = rmsnorm(h2) -> blocked hi/lo
  rmsnorm_split_kernel<<<ROWS, 256, 0, m>>>(h2, mlp_norm_w, nullptr,
                                            bf + BF_3H, bf + BF_3L);

  // u = swiglu(h3 @ Wg) -> blocked hi/lo (fused epilogue)
  bf16gemm_kernel<<<dim3(44, 16), 256, GEMM_SMEM, m>>>(
      bf + BF_3H, bf + BF_3L, bf + BF_WGH, bf + BF_WGL, nullptr, nullptr,
      bf + BF_UH, bf + BF_UL, TWOI, 32);

  // out = u @ Wd + h2
  bf16gemm_kernel<<<dim3(8, 16), 256, GEMM_SMEM, m>>>(
      bf + BF_UH, bf + BF_UL, bf + BF_WDH, bf + BF_WDL, h2, out,
      nullptr, nullptr, 1024, 88);
}